// round 1
// baseline (speedup 1.0000x reference)
#include <cuda_runtime.h>
#include <cstdint>
#include <math.h>

// Problem dims (fixed)
#define VV 50257
#define EE 1024
#define HH 1024
#define BB 64
#define TT 512
#define G4 4096        // 4*H
#define GRID_REC 128   // persistent blocks for recurrence (<=148 SMs, 1/SM by smem)
#define JW 8           // H-columns owned per recurrent block (128*8 = 1024)

// -------- scratch (no allocations allowed: __device__ globals) --------
__device__ float    g_Xp[(size_t)TT * BB * G4];   // 512 MB: precomputed x_t @ W_ih^T
__device__ float    g_h[2][BB * HH];              // h ping-pong
__device__ unsigned g_cnt;                        // grid barrier state (zero-init)
__device__ unsigned g_gen;

// -------- helpers --------
__device__ __forceinline__ float tf32r(float x) {
    uint32_t u;
    asm("cvt.rna.tf32.f32 %0, %1;" : "=r"(u) : "f"(x));
    return __uint_as_float(u);
}

__device__ __forceinline__ void mma8(float* acc, const uint32_t* a, uint32_t b0, uint32_t b1) {
    asm volatile(
        "mma.sync.aligned.m16n8k8.row.col.f32.tf32.tf32.f32 "
        "{%0,%1,%2,%3}, {%4,%5,%6,%7}, {%8,%9}, {%0,%1,%2,%3};\n"
        : "+f"(acc[0]), "+f"(acc[1]), "+f"(acc[2]), "+f"(acc[3])
        : "r"(a[0]), "r"(a[1]), "r"(a[2]), "r"(a[3]), "r"(b0), "r"(b1));
}

__device__ __forceinline__ float sigm(float x) { return 1.f / (1.f + expf(-x)); }

// Hand-rolled grid barrier (capturable, deterministic; g_gen monotonically grows
// across replays, g_cnt returns to 0 after every barrier).
__device__ __forceinline__ void grid_barrier() {
    __threadfence();
    __syncthreads();
    if (threadIdx.x == 0) {
        volatile unsigned* vg = &g_gen;
        unsigned my = *vg;
        if (atomicAdd(&g_cnt, 1u) == GRID_REC - 1u) {
            g_cnt = 0u;
            __threadfence();
            atomicAdd(&g_gen, 1u);
        } else {
            while (*vg == my) {}
        }
        __threadfence();
    }
    __syncthreads();
}

// ============================================================================
// Kernel 1: input projection  Xp[t*B+b, :] = emb[tok[b,t]] @ W_ih^T
// GEMM M=32768 (gathered rows), N=4096, K=1024. Tile 128x128x32, tf32 mma.
// ============================================================================
__global__ __launch_bounds__(256) void proj_kernel(
    const int* __restrict__ tok, const float* __restrict__ emb,
    const float* __restrict__ Wih) {
    __shared__ float As[128][36];
    __shared__ float Bs[128][36];
    __shared__ int   tokA[128];

    const int tid = threadIdx.x;
    const int m0  = blockIdx.y * 128;
    const int n0  = blockIdx.x * 128;

    if (tid < 128) {
        int r = m0 + tid;
        int t = r >> 6, b = r & 63;   // r = t*64 + b
        tokA[tid] = tok[b * TT + t];
    }
    __syncthreads();

    const int w = tid >> 5, lane = tid & 31;
    const int grp = lane >> 2, tig = lane & 3;
    const int wm = (w & 3) * 32;   // 4 warp-rows of 32
    const int wn = (w >> 2) * 64;  // 2 warp-cols of 64

    float acc[2][8][4];
#pragma unroll
    for (int mi = 0; mi < 2; mi++)
#pragma unroll
        for (int ni = 0; ni < 8; ni++)
#pragma unroll
            for (int q = 0; q < 4; q++) acc[mi][ni][q] = 0.f;

    for (int k0 = 0; k0 < EE; k0 += 32) {
        for (int i = tid; i < 1024; i += 256) {
            int row = i >> 3, c4 = (i & 7) * 4;
            float4 v = *(const float4*)(emb + (size_t)tokA[row] * EE + k0 + c4);
            As[row][c4]     = tf32r(v.x);
            As[row][c4 + 1] = tf32r(v.y);
            As[row][c4 + 2] = tf32r(v.z);
            As[row][c4 + 3] = tf32r(v.w);
        }
        for (int i = tid; i < 1024; i += 256) {
            int row = i >> 3, c4 = (i & 7) * 4;
            float4 v = *(const float4*)(Wih + (size_t)(n0 + row) * EE + k0 + c4);
            Bs[row][c4]     = tf32r(v.x);
            Bs[row][c4 + 1] = tf32r(v.y);
            Bs[row][c4 + 2] = tf32r(v.z);
            Bs[row][c4 + 3] = tf32r(v.w);
        }
        __syncthreads();
#pragma unroll
        for (int kk = 0; kk < 32; kk += 8) {
            uint32_t a[2][4];
#pragma unroll
            for (int mi = 0; mi < 2; mi++) {
                int r = wm + mi * 16;
                a[mi][0] = __float_as_uint(As[r + grp][kk + tig]);
                a[mi][1] = __float_as_uint(As[r + grp + 8][kk + tig]);
                a[mi][2] = __float_as_uint(As[r + grp][kk + tig + 4]);
                a[mi][3] = __float_as_uint(As[r + grp + 8][kk + tig + 4]);
            }
#pragma unroll
            for (int ni = 0; ni < 8; ni++) {
                int c = wn + ni * 8;
                uint32_t b0 = __float_as_uint(Bs[c + grp][kk + tig]);
                uint32_t b1 = __float_as_uint(Bs[c + grp][kk + tig + 4]);
                mma8(acc[0][ni], a[0], b0, b1);
                mma8(acc[1][ni], a[1], b0, b1);
            }
        }
        __syncthreads();
    }
#pragma unroll
    for (int mi = 0; mi < 2; mi++) {
#pragma unroll
        for (int ni = 0; ni < 8; ni++) {
            int r0 = m0 + wm + mi * 16 + grp;
            int c0 = n0 + wn + ni * 8 + tig * 2;
            g_Xp[(size_t)r0 * G4 + c0]           = acc[mi][ni][0];
            g_Xp[(size_t)r0 * G4 + c0 + 1]       = acc[mi][ni][1];
            g_Xp[(size_t)(r0 + 8) * G4 + c0]     = acc[mi][ni][2];
            g_Xp[(size_t)(r0 + 8) * G4 + c0 + 1] = acc[mi][ni][3];
        }
    }
}

// ============================================================================
// Kernel 2: persistent LSTM recurrence.
// 128 blocks; block nb owns H-cols [nb*8, nb*8+8). Its 32 W_hh rows (i,f,g,o x 8)
// live tf32-rounded in SMEM for all 512 steps; its c-slice lives in SMEM.
// Per step: gates(64x32) = h(64x1024) @ Wslice^T, + Xp, elementwise, write h slice.
// ============================================================================
extern __shared__ float dynsm[];

__global__ __launch_bounds__(256, 1) void lstm_kernel(
    const float* __restrict__ Whh, float* __restrict__ out) {
    float* Ws  = dynsm;               // [32][1028]  (pad 4 -> conflict-free b-frags)
    float* hA  = Ws + 32 * 1028;      // [64][68]    h k-chunk staging
    float* gts = hA + 64 * 68;        // [64][33]    gate tile
    float* cS  = gts + 64 * 33;       // [512]       c slice (persistent)

    const int tid = threadIdx.x;
    const int nb  = blockIdx.x;
    const int j0  = nb * JW;

    // Load W_hh slice (rows gi*1024 + j0 + jj for gi=0..3, jj=0..7), pre-rounded tf32.
    for (int i = tid; i < 32 * 256; i += 256) {
        int row = i >> 8;            // local n: 0..31
        int c4  = (i & 255) * 4;     // k: 0..1020
        int gi = row >> 3, jj = row & 7;
        float4 v = *(const float4*)(Whh + (size_t)(gi * HH + j0 + jj) * HH + c4);
        Ws[row * 1028 + c4]     = tf32r(v.x);
        Ws[row * 1028 + c4 + 1] = tf32r(v.y);
        Ws[row * 1028 + c4 + 2] = tf32r(v.z);
        Ws[row * 1028 + c4 + 3] = tf32r(v.w);
    }
    // Zero initial h slice (buffer 0) and c slice.
    for (int i = tid; i < BB * JW; i += 256) {
        int b = i >> 3, jj = i & 7;
        g_h[0][b * HH + j0 + jj] = 0.f;
        cS[i] = 0.f;
    }
    grid_barrier();

    const int w = tid >> 5, lane = tid & 31;
    const int grp = lane >> 2, tig = lane & 3;
    const int mrow  = (w & 3) * 16;   // 4 m16 tiles cover M=64
    const int nbase = (w >> 2) * 16;  // 2 warp-groups x 2 n8 tiles cover N=32

    for (int t = 0; t < TT; t++) {
        const float* hin  = g_h[t & 1];
        float*       hout = g_h[(t + 1) & 1];

        float acc[2][4];
#pragma unroll
        for (int ni = 0; ni < 2; ni++)
#pragma unroll
            for (int q = 0; q < 4; q++) acc[ni][q] = 0.f;

        for (int k0 = 0; k0 < HH; k0 += 64) {
            for (int i = tid; i < 1024; i += 256) {
                int row = i >> 4, c4 = (i & 15) * 4;
                float4 v = *(const float4*)(hin + row * HH + k0 + c4);
                hA[row * 68 + c4]     = tf32r(v.x);
                hA[row * 68 + c4 + 1] = tf32r(v.y);
                hA[row * 68 + c4 + 2] = tf32r(v.z);
                hA[row * 68 + c4 + 3] = tf32r(v.w);
            }
            __syncthreads();
#pragma unroll
            for (int kk = 0; kk < 64; kk += 8) {
                uint32_t a[4];
                a[0] = __float_as_uint(hA[(mrow + grp) * 68 + kk + tig]);
                a[1] = __float_as_uint(hA[(mrow + grp + 8) * 68 + kk + tig]);
                a[2] = __float_as_uint(hA[(mrow + grp) * 68 + kk + tig + 4]);
                a[3] = __float_as_uint(hA[(mrow + grp + 8) * 68 + kk + tig + 4]);
#pragma unroll
                for (int ni = 0; ni < 2; ni++) {
                    int c = nbase + ni * 8;
                    uint32_t b0 = __float_as_uint(Ws[(c + grp) * 1028 + k0 + kk + tig]);
                    uint32_t b1 = __float_as_uint(Ws[(c + grp) * 1028 + k0 + kk + tig + 4]);
                    mma8(acc[ni], a, b0, b1);
                }
            }
            __syncthreads();
        }
        // Dump gate tile to smem.
#pragma unroll
        for (int ni = 0; ni < 2; ni++) {
            int c0 = nbase + ni * 8 + tig * 2;
            gts[(mrow + grp) * 33 + c0]         = acc[ni][0];
            gts[(mrow + grp) * 33 + c0 + 1]     = acc[ni][1];
            gts[(mrow + grp + 8) * 33 + c0]     = acc[ni][2];
            gts[(mrow + grp + 8) * 33 + c0 + 1] = acc[ni][3];
        }
        __syncthreads();
        // Elementwise LSTM update for the owned 64x8 slice.
        for (int i = tid; i < 512; i += 256) {
            int b = i >> 3, jj = i & 7;
            const float* xp = g_Xp + ((size_t)t * BB + b) * G4 + j0 + jj;
            float ig = gts[b * 33 + jj]          + xp[0];
            float fg = gts[b * 33 + 8 + jj]      + xp[HH];
            float gg = gts[b * 33 + 16 + jj]     + xp[2 * HH];
            float og = gts[b * 33 + 24 + jj]     + xp[3 * HH];
            float c2 = sigm(fg) * cS[i] + sigm(ig) * tanhf(gg);
            float h2 = sigm(og) * tanhf(c2);
            cS[i] = c2;
            hout[b * HH + j0 + jj] = h2;
            if (t == TT - 1) {
                out[(size_t)BB * VV + b * HH + j0 + jj]           = h2;
                out[(size_t)BB * VV + BB * HH + b * HH + j0 + jj] = c2;
            }
        }
        grid_barrier();
    }
}

// ============================================================================
// Kernel 3: classifier  logits[b, n] = h @ W_cls^T + b_cls.
// M=64, N=50257 (tail-guarded), K=1024. Tile 64x128x32, tf32 mma.
// ============================================================================
__global__ __launch_bounds__(256) void cls_kernel(
    const float* __restrict__ Wc, const float* __restrict__ bc,
    float* __restrict__ out) {
    __shared__ float As[64][36];
    __shared__ float Bs[128][36];

    const int tid = threadIdx.x;
    const int n0  = blockIdx.x * 128;
    const int w = tid >> 5, lane = tid & 31;
    const int grp = lane >> 2, tig = lane & 3;
    const int wm = (w & 1) * 32;   // 2 warp-rows of 32
    const int wn = (w >> 1) * 32;  // 4 warp-cols of 32
    const float* __restrict__ h = g_h[0];  // final h: step 511 wrote buffer (512&1)=0

    float acc[2][4][4];
#pragma unroll
    for (int mi = 0; mi < 2; mi++)
#pragma unroll
        for (int ni = 0; ni < 4; ni++)
#pragma unroll
            for (int q = 0; q < 4; q++) acc[mi][ni][q] = 0.f;

    for (int k0 = 0; k0 < HH; k0 += 32) {
        for (int i = tid; i < 512; i += 256) {
            int row = i >> 3, c4 = (i & 7) * 4;
            float4 v = *(const float4*)(h + row * HH + k0 + c4);
            As[row][c4]     = tf32r(v.x);
            As[row][c4 + 1] = tf32r(v.y);
            As[row][c4 + 2] = tf32r(v.z);
            As[row][c4 + 3] = tf32r(v.w);
        }
        for (int i = tid; i < 1024; i += 256) {
            int row = i >> 3, c4 = (i & 7) * 4;
            int nr = n0 + row;
            float4 v = make_float4(0.f, 0.f, 0.f, 0.f);
            if (nr < VV) v = *(const float4*)(Wc + (size_t)nr * HH + k0 + c4);
            Bs[row][c4]     = tf32r(v.x);
            Bs[row][c4 + 1] = tf32r(v.y);
            Bs[row][c4 + 2] = tf32r(v.z);
            Bs[row][c4 + 3] = tf32r(v.w);
        }
        __syncthreads();
#pragma unroll
        for (int kk = 0; kk < 32; kk += 8) {
            uint32_t a[2][4];
#pragma unroll
            for (int mi = 0; mi < 2; mi++) {
                int r = wm + mi * 16;
                a[mi][0] = __float_as_uint(As[r + grp][kk + tig]);
                a[mi][1] = __float_as_uint(As[r + grp + 8][kk + tig]);
                a[mi][2] = __float_as_uint(As[r + grp][kk + tig + 4]);
                a[mi][3] = __float_as_uint(As[r + grp + 8][kk + tig + 4]);
            }
#pragma unroll
            for (int ni = 0; ni < 4; ni++) {
                int c = wn + ni * 8;
                uint32_t b0 = __float_as_uint(Bs[c + grp][kk + tig]);
                uint32_t b1 = __float_as_uint(Bs[c + grp][kk + tig + 4]);
                mma8(acc[0][ni], a[0], b0, b1);
                mma8(acc[1][ni], a[1], b0, b1);
            }
        }
        __syncthreads();
    }
#pragma unroll
    for (int mi = 0; mi < 2; mi++) {
#pragma unroll
        for (int ni = 0; ni < 4; ni++) {
            int r0 = wm + mi * 16 + grp;
            int c0 = n0 + wn + ni * 8 + tig * 2;
            if (c0 < VV) {
                out[(size_t)r0 * VV + c0]       = acc[mi][ni][0] + bc[c0];
                out[(size_t)(r0 + 8) * VV + c0] = acc[mi][ni][2] + bc[c0];
            }
            if (c0 + 1 < VV) {
                out[(size_t)r0 * VV + c0 + 1]       = acc[mi][ni][1] + bc[c0 + 1];
                out[(size_t)(r0 + 8) * VV + c0 + 1] = acc[mi][ni][3] + bc[c0 + 1];
            }
        }
    }
}

// ============================================================================
extern "C" void kernel_launch(void* const* d_in, const int* in_sizes, int n_in,
                              void* d_out, int out_size) {
    const int*   tok  = (const int*)d_in[0];
    const float* emb  = (const float*)d_in[1];
    const float* Wih  = (const float*)d_in[2];
    const float* Whh  = (const float*)d_in[3];
    const float* Wcls = (const float*)d_in[4];
    const float* bcls = (const float*)d_in[5];
    float*       out  = (float*)d_out;

    const int lstm_smem = (32 * 1028 + 64 * 68 + 64 * 33 + 512) * 4;  // 159488 B
    cudaFuncSetAttribute(lstm_kernel, cudaFuncAttributeMaxDynamicSharedMemorySize,
                         lstm_smem);

    proj_kernel<<<dim3(G4 / 128, (TT * BB) / 128), 256>>>(tok, emb, Wih);
    lstm_kernel<<<GRID_REC, 256, lstm_smem>>>(Whh, out);
    cls_kernel<<<(VV + 127) / 128, 256>>>(Wcls, bcls, out);
}

// round 5
// speedup vs baseline: 2.2793x; 2.2793x over previous
#include <cuda_runtime.h>
#include <cstdint>
#include <math.h>

// Problem dims (fixed)
#define VV 50257
#define EE 1024
#define HH 1024
#define BB 64
#define TT 512
#define G4 4096        // 4*H
#define GRID_REC 128   // persistent blocks for recurrence
#define JW 8           // H-columns owned per recurrent block (128*8 = 1024)
#define MROWS (TT*BB)  // 32768 gathered rows

// -------- scratch (no allocations allowed: __device__ globals) --------
__device__ float    g_Xp[(size_t)TT * BB * G4];   // 512 MB: x_t @ W_ih^T
__device__ float    g_Xg[(size_t)MROWS * EE];     // 128 MB: gathered+rounded emb rows
__device__ float    g_Wr[(size_t)G4 * EE];        // 16 MB: rounded W_ih
__device__ float    g_h[2][BB * HH];              // h ping-pong (tf32-rounded values)
__device__ unsigned g_cnt;                        // grid barrier state (zero-init)
__device__ unsigned g_gen;

// -------- helpers --------
__device__ __forceinline__ float tf32r(float x) {
    uint32_t u;
    asm("cvt.rna.tf32.f32 %0, %1;" : "=r"(u) : "f"(x));
    return __uint_as_float(u);
}

__device__ __forceinline__ void cpasync16(uint32_t smem_dst, const void* gsrc) {
    asm volatile("cp.async.cg.shared.global [%0], [%1], 16;\n"
                 :: "r"(smem_dst), "l"(gsrc));
}
__device__ __forceinline__ void cpcommit() {
    asm volatile("cp.async.commit_group;\n");
}
__device__ __forceinline__ void cpwait0() {
    asm volatile("cp.async.wait_group 0;\n");
}

__device__ __forceinline__ void mma8(float* acc, const uint32_t* a, uint32_t b0, uint32_t b1) {
    asm volatile(
        "mma.sync.aligned.m16n8k8.row.col.f32.tf32.tf32.f32 "
        "{%0,%1,%2,%3}, {%4,%5,%6,%7}, {%8,%9}, {%0,%1,%2,%3};\n"
        : "+f"(acc[0]), "+f"(acc[1]), "+f"(acc[2]), "+f"(acc[3])
        : "r"(a[0]), "r"(a[1]), "r"(a[2]), "r"(a[3]), "r"(b0), "r"(b1));
}

__device__ __forceinline__ float sigm(float x) { return 1.f / (1.f + expf(-x)); }

__device__ __forceinline__ void grid_barrier() {
    __threadfence();
    __syncthreads();
    if (threadIdx.x == 0) {
        volatile unsigned* vg = &g_gen;
        unsigned my = *vg;
        if (atomicAdd(&g_cnt, 1u) == GRID_REC - 1u) {
            g_cnt = 0u;
            __threadfence();
            atomicAdd(&g_gen, 1u);
        } else {
            while (*vg == my) {}
        }
        __threadfence();
    }
    __syncthreads();
}

// ============================================================================
// Kernel 0: prep. Row r<32768: Xg[r] = tf32(emb[tok]); else Wr = tf32(Wih).
// ============================================================================
__global__ __launch_bounds__(256) void prep_kernel(
    const int* __restrict__ tok, const float* __restrict__ emb,
    const float* __restrict__ Wih) {
    int row = blockIdx.x;
    const float* src;
    float* dst;
    if (row < MROWS) {
        int t = row >> 6, b = row & 63;
        src = emb + (size_t)tok[b * TT + t] * EE;
        dst = g_Xg + (size_t)row * EE;
    } else {
        int r = row - MROWS;
        src = Wih + (size_t)r * EE;
        dst = g_Wr + (size_t)r * EE;
    }
    int c = threadIdx.x * 4;
    float4 v = *(const float4*)(src + c);
    v.x = tf32r(v.x); v.y = tf32r(v.y); v.z = tf32r(v.z); v.w = tf32r(v.w);
    *(float4*)(dst + c) = v;
}

// ============================================================================
// Kernel 1: input projection  Xp = Xg @ Wr^T.
// M=32768, N=4096, K=1024. Tile 128x128, k-chunk 32, cp.async double buffer.
// ============================================================================
extern __shared__ float dynsm[];

__global__ __launch_bounds__(256) void proj_kernel() {
    float* As = dynsm;            // [2][128][36]
    float* Bs = dynsm + 9216;     // [2][128][36]

    const int tid = threadIdx.x;
    const int m0  = blockIdx.y * 128;
    const int n0  = blockIdx.x * 128;

    uint32_t as_u = (uint32_t)__cvta_generic_to_shared(As);
    uint32_t bs_u = (uint32_t)__cvta_generic_to_shared(Bs);

    const int w = tid >> 5, lane = tid & 31;
    const int grp = lane >> 2, tig = lane & 3;
    const int wm = (w & 3) * 32;   // 4 warp-rows of 32
    const int wn = (w >> 2) * 64;  // 2 warp-cols of 64

    float acc[2][8][4];
#pragma unroll
    for (int mi = 0; mi < 2; mi++)
#pragma unroll
        for (int ni = 0; ni < 8; ni++)
#pragma unroll
            for (int q = 0; q < 4; q++) acc[mi][ni][q] = 0.f;

    // copy chunk: 128 rows x 32 floats per matrix = 1024 x 16B each
    auto copy_chunk = [&](int buf, int k0) {
#pragma unroll
        for (int i = tid; i < 1024; i += 256) {
            int row = i >> 3, seg = (i & 7) * 4;
            cpasync16(as_u + (buf * 4608 + row * 36 + seg) * 4,
                      g_Xg + (size_t)(m0 + row) * EE + k0 + seg);
            cpasync16(bs_u + (buf * 4608 + row * 36 + seg) * 4,
                      g_Wr + (size_t)(n0 + row) * EE + k0 + seg);
        }
        cpcommit();
    };

    copy_chunk(0, 0);

    for (int c = 0; c < 32; c++) {
        cpwait0();
        __syncthreads();
        if (c < 31) copy_chunk((c + 1) & 1, (c + 1) * 32);
        const float* A = As + (c & 1) * 4608;
        const float* B = Bs + (c & 1) * 4608;
#pragma unroll
        for (int kk = 0; kk < 32; kk += 8) {
            uint32_t a[2][4];
#pragma unroll
            for (int mi = 0; mi < 2; mi++) {
                int r = wm + mi * 16;
                a[mi][0] = __float_as_uint(A[(r + grp) * 36 + kk + tig]);
                a[mi][1] = __float_as_uint(A[(r + grp + 8) * 36 + kk + tig]);
                a[mi][2] = __float_as_uint(A[(r + grp) * 36 + kk + tig + 4]);
                a[mi][3] = __float_as_uint(A[(r + grp + 8) * 36 + kk + tig + 4]);
            }
#pragma unroll
            for (int ni = 0; ni < 8; ni++) {
                int cc = wn + ni * 8;
                uint32_t b0 = __float_as_uint(B[(cc + grp) * 36 + kk + tig]);
                uint32_t b1 = __float_as_uint(B[(cc + grp) * 36 + kk + tig + 4]);
                mma8(acc[0][ni], a[0], b0, b1);
                mma8(acc[1][ni], a[1], b0, b1);
            }
        }
    }
#pragma unroll
    for (int mi = 0; mi < 2; mi++) {
#pragma unroll
        for (int ni = 0; ni < 8; ni++) {
            int r0 = m0 + wm + mi * 16 + grp;
            int c0 = n0 + wn + ni * 8 + tig * 2;
            g_Xp[(size_t)r0 * G4 + c0]           = acc[mi][ni][0];
            g_Xp[(size_t)r0 * G4 + c0 + 1]       = acc[mi][ni][1];
            g_Xp[(size_t)(r0 + 8) * G4 + c0]     = acc[mi][ni][2];
            g_Xp[(size_t)(r0 + 8) * G4 + c0 + 1] = acc[mi][ni][3];
        }
    }
}

// ============================================================================
// Kernel 2: persistent LSTM recurrence (cp.async pipelined, k-chunk 128).
// Block nb owns H-cols [nb*8, nb*8+8). W_hh slice (tf32) + c-slice in SMEM.
// ============================================================================
__global__ __launch_bounds__(256, 1) void lstm_kernel(
    const float* __restrict__ Whh, float* __restrict__ out) {
    float* Ws  = dynsm;               // [32][1028]
    float* hA  = Ws + 32 * 1028;      // [2][64][132]
    float* gts = hA + 2 * 64 * 132;   // [64][33]
    float* cS  = gts + 64 * 33;       // [512]

    const int tid = threadIdx.x;
    const int nb  = blockIdx.x;
    const int j0  = nb * JW;
    uint32_t ha_u = (uint32_t)__cvta_generic_to_shared(hA);

    // Load W_hh slice, pre-rounded tf32.
    for (int i = tid; i < 32 * 256; i += 256) {
        int row = i >> 8;            // local n: 0..31
        int c4  = (i & 255) * 4;     // k
        int gi = row >> 3, jj = row & 7;
        float4 v = *(const float4*)(Whh + (size_t)(gi * HH + j0 + jj) * HH + c4);
        Ws[row * 1028 + c4]     = tf32r(v.x);
        Ws[row * 1028 + c4 + 1] = tf32r(v.y);
        Ws[row * 1028 + c4 + 2] = tf32r(v.z);
        Ws[row * 1028 + c4 + 3] = tf32r(v.w);
    }
    for (int i = tid; i < BB * JW; i += 256) {
        int b = i >> 3, jj = i & 7;
        g_h[0][b * HH + j0 + jj] = 0.f;
        cS[i] = 0.f;
    }
    grid_barrier();

    const int w = tid >> 5, lane = tid & 31;
    const int grp = lane >> 2, tig = lane & 3;
    const int mrow  = (w & 3) * 16;   // 4 m16 tiles cover M=64
    const int nbase = (w >> 2) * 16;  // 2x2 n8 tiles cover N=32

    // elementwise ownership: items tid and tid+256
    const int eb0 = tid >> 3,          ej0 = tid & 7;
    const int eb1 = (tid + 256) >> 3,  ej1 = (tid + 256) & 7;

    for (int t = 0; t < TT; t++) {
        const float* hin  = g_h[t & 1];
        float*       hout = g_h[(t + 1) & 1];

        // Prefetch Xp gate slices into registers (hidden behind gemm).
        float xg0[4], xg1[4];
        {
            const float* p0 = g_Xp + ((size_t)t * BB + eb0) * G4 + j0 + ej0;
            const float* p1 = g_Xp + ((size_t)t * BB + eb1) * G4 + j0 + ej1;
#pragma unroll
            for (int g = 0; g < 4; g++) { xg0[g] = __ldg(p0 + g * HH); xg1[g] = __ldg(p1 + g * HH); }
        }

        float acc[2][4];
#pragma unroll
        for (int ni = 0; ni < 2; ni++)
#pragma unroll
            for (int q = 0; q < 4; q++) acc[ni][q] = 0.f;

        // copy chunk: 64 rows x 128 floats = 2048 x 16B
        auto copy_chunk = [&](int buf, int k0) {
#pragma unroll
            for (int i = tid; i < 2048; i += 256) {
                int row = i >> 5, seg = (i & 31) * 4;
                cpasync16(ha_u + (buf * 8448 + row * 132 + seg) * 4,
                          hin + (size_t)row * HH + k0 + seg);
            }
            cpcommit();
        };

        copy_chunk(0, 0);
        for (int c = 0; c < 8; c++) {
            cpwait0();
            __syncthreads();
            if (c < 7) copy_chunk((c + 1) & 1, (c + 1) * 128);
            const float* Hc = hA + (c & 1) * 8448;
            const int kbase = c * 128;
#pragma unroll
            for (int kk = 0; kk < 128; kk += 8) {
                uint32_t a[4];
                a[0] = __float_as_uint(Hc[(mrow + grp) * 132 + kk + tig]);
                a[1] = __float_as_uint(Hc[(mrow + grp + 8) * 132 + kk + tig]);
                a[2] = __float_as_uint(Hc[(mrow + grp) * 132 + kk + tig + 4]);
                a[3] = __float_as_uint(Hc[(mrow + grp + 8) * 132 + kk + tig + 4]);
#pragma unroll
                for (int ni = 0; ni < 2; ni++) {
                    int cc = nbase + ni * 8;
                    uint32_t b0 = __float_as_uint(Ws[(cc + grp) * 1028 + kbase + kk + tig]);
                    uint32_t b1 = __float_as_uint(Ws[(cc + grp) * 1028 + kbase + kk + tig + 4]);
                    mma8(acc[ni], a, b0, b1);
                }
            }
        }
        // Dump gate tile to smem.
#pragma unroll
        for (int ni = 0; ni < 2; ni++) {
            int c0 = nbase + ni * 8 + tig * 2;
            gts[(mrow + grp) * 33 + c0]         = acc[ni][0];
            gts[(mrow + grp) * 33 + c0 + 1]     = acc[ni][1];
            gts[(mrow + grp + 8) * 33 + c0]     = acc[ni][2];
            gts[(mrow + grp + 8) * 33 + c0 + 1] = acc[ni][3];
        }
        __syncthreads();
        // Elementwise LSTM update for the owned 64x8 slice (2 items/thread).
        {
            float ig = gts[eb0 * 33 + ej0]      + xg0[0];
            float fg = gts[eb0 * 33 + 8 + ej0]  + xg0[1];
            float gg = gts[eb0 * 33 + 16 + ej0] + xg0[2];
            float og = gts[eb0 * 33 + 24 + ej0] + xg0[3];
            float c2 = sigm(fg) * cS[tid] + sigm(ig) * tanhf(gg);
            float h2 = sigm(og) * tanhf(c2);
            cS[tid] = c2;
            hout[eb0 * HH + j0 + ej0] = tf32r(h2);
            if (t == TT - 1) {
                out[(size_t)BB * VV + eb0 * HH + j0 + ej0]           = h2;
                out[(size_t)BB * VV + BB * HH + eb0 * HH + j0 + ej0] = c2;
            }
        }
        {
            float ig = gts[eb1 * 33 + ej1]      + xg1[0];
            float fg = gts[eb1 * 33 + 8 + ej1]  + xg1[1];
            float gg = gts[eb1 * 33 + 16 + ej1] + xg1[2];
            float og = gts[eb1 * 33 + 24 + ej1] + xg1[3];
            float c2 = sigm(fg) * cS[tid + 256] + sigm(ig) * tanhf(gg);
            float h2 = sigm(og) * tanhf(c2);
            cS[tid + 256] = c2;
            hout[eb1 * HH + j0 + ej1] = tf32r(h2);
            if (t == TT - 1) {
                out[(size_t)BB * VV + eb1 * HH + j0 + ej1]           = h2;
                out[(size_t)BB * VV + BB * HH + eb1 * HH + j0 + ej1] = c2;
            }
        }
        grid_barrier();
    }
}

// ============================================================================
// Kernel 3: classifier  logits = h @ W_cls^T + b_cls. M=64, N=50257, K=1024.
// ============================================================================
__global__ __launch_bounds__(256) void cls_kernel(
    const float* __restrict__ Wc, const float* __restrict__ bc,
    float* __restrict__ out) {
    __shared__ float As[64][36];
    __shared__ float Bs[128][36];

    const int tid = threadIdx.x;
    const int n0  = blockIdx.x * 128;
    const int w = tid >> 5, lane = tid & 31;
    const int grp = lane >> 2, tig = lane & 3;
    const int wm = (w & 1) * 32;
    const int wn = (w >> 1) * 32;
    const float* __restrict__ h = g_h[0];  // final h written at t=511 -> buf 0

    float acc[2][4][4];
#pragma unroll
    for (int mi = 0; mi < 2; mi++)
#pragma unroll
        for (int ni = 0; ni < 4; ni++)
#pragma unroll
            for (int q = 0; q < 4; q++) acc[mi][ni][q] = 0.f;

    for (int k0 = 0; k0 < HH; k0 += 32) {
        for (int i = tid; i < 512; i += 256) {
            int row = i >> 3, c4 = (i & 7) * 4;
            float4 v = *(const float4*)(h + row * HH + k0 + c4);
            As[row][c4]     = v.x;   // h already tf32-rounded
            As[row][c4 + 1] = v.y;
            As[row][c4 + 2] = v.z;
            As[row][c4 + 3] = v.w;
        }
        for (int i = tid; i < 1024; i += 256) {
            int row = i >> 3, c4 = (i & 7) * 4;
            int nr = n0 + row;
            float4 v = make_float4(0.f, 0.f, 0.f, 0.f);
            if (nr < VV) v = *(const float4*)(Wc + (size_t)nr * HH + k0 + c4);
            Bs[row][c4]     = tf32r(v.x);
            Bs[row][c4 + 1] = tf32r(v.y);
            Bs[row][c4 + 2] = tf32r(v.z);
            Bs[row][c4 + 3] = tf32r(v.w);
        }
        __syncthreads();
#pragma unroll
        for (int kk = 0; kk < 32; kk += 8) {
            uint32_t a[2][4];
#pragma unroll
            for (int mi = 0; mi < 2; mi++) {
                int r = wm + mi * 16;
                a[mi][0] = __float_as_uint(As[r + grp][kk + tig]);
                a[mi][1] = __float_as_uint(As[r + grp + 8][kk + tig]);
                a[mi][2] = __float_as_uint(As[r + grp][kk + tig + 4]);
                a[mi][3] = __float_as_uint(As[r + grp + 8][kk + tig + 4]);
            }
#pragma unroll
            for (int ni = 0; ni < 4; ni++) {
                int c = wn + ni * 8;
                uint32_t b0 = __float_as_uint(Bs[c + grp][kk + tig]);
                uint32_t b1 = __float_as_uint(Bs[c + grp][kk + tig + 4]);
                mma8(acc[0][ni], a[0], b0, b1);
                mma8(acc[1][ni], a[1], b0, b1);
            }
        }
        __syncthreads();
    }
#pragma unroll
    for (int mi = 0; mi < 2; mi++) {
#pragma unroll
        for (int ni = 0; ni < 4; ni++) {
            int r0 = wm + mi * 16 + grp;
            int c0 = n0 + wn + ni * 8 + tig * 2;
            if (c0 < VV) {
                out[(size_t)r0 * VV + c0]       = acc[mi][ni][0] + bc[c0];
                out[(size_t)(r0 + 8) * VV + c0] = acc[mi][ni][2] + bc[c0];
            }
            if (c0 + 1 < VV) {
                out[(size_t)r0 * VV + c0 + 1]       = acc[mi][ni][1] + bc[c0 + 1];
                out[(size_t)(r0 + 8) * VV + c0 + 1] = acc[mi][ni][3] + bc[c0 + 1];
            }
        }
    }
}

// ============================================================================
extern "C" void kernel_launch(void* const* d_in, const int* in_sizes, int n_in,
                              void* d_out, int out_size) {
    const int*   tok  = (const int*)d_in[0];
    const float* emb  = (const float*)d_in[1];
    const float* Wih  = (const float*)d_in[2];
    const float* Whh  = (const float*)d_in[3];
    const float* Wcls = (const float*)d_in[4];
    const float* bcls = (const float*)d_in[5];
    float*       out  = (float*)d_out;

    const int proj_smem = (2 * 128 * 36 * 2) * 4;                       // 73,728 B
    const int lstm_smem = (32 * 1028 + 2 * 64 * 132 + 64 * 33 + 512) * 4; // 209,664 B
    cudaFuncSetAttribute(proj_kernel, cudaFuncAttributeMaxDynamicSharedMemorySize,
                         proj_smem);
    cudaFuncSetAttribute(lstm_kernel, cudaFuncAttributeMaxDynamicSharedMemorySize,
                         lstm_smem);

    prep_kernel<<<MROWS + G4, 256>>>(tok, emb, Wih);
    proj_kernel<<<dim3(G4 / 128, MROWS / 128), 256, proj_smem>>>();
    lstm_kernel<<<GRID_REC, 256, lstm_smem>>>(Whh, out);
    cls_kernel<<<(VV + 127) / 128, 256>>>(Wcls, bcls, out);
}